// round 16
// baseline (speedup 1.0000x reference)
#include <cuda_runtime.h>

#define M_ROWS 12288
#define N_COLS 12288
#define D_DIM  128
#define INV_T  (1.0f/0.07f)
#define IDXCAP 128
#define RCAP   64                       // smem-staged neighbor rows
#define RPITCH 132                      // floats per staged row (528B, pad kills conflicts)
#define SCAN_TB 256
#define SCAN_IT ((N_COLS/4)/SCAN_TB)    // 12 int4 loads per thread

// static scratch (allocation-free)
__device__ float g_xa[(size_t)M_ROWS * D_DIM];
__device__ int   g_cnt[M_ROWS];
__device__ int   g_idx[(size_t)M_ROWS * IDXCAP];

// ---------------------------------------------------------------------------
// Kernel S+A fused (R10-proven, 98.2us): adjacency stream + matvec riding
// the idle issue slots. Byte-identical to R10. Do not disturb.
// ---------------------------------------------------------------------------
__global__ void __launch_bounds__(SCAN_TB) scan_xw_kernel(const int4*   __restrict__ adj4,
                                                          const float4* __restrict__ xanchor4,
                                                          const float4* __restrict__ W4) {
    __shared__ int    s_cnt;
    __shared__ float4 s_x[D_DIM / 4];
    __shared__ float4 s_part[8][D_DIM / 4];

    const int m   = blockIdx.x;
    const int tid = threadIdx.x;

    if (tid == 0) s_cnt = 0;
    if (tid < 32) s_x[tid] = xanchor4[(size_t)m * 32 + tid];

    const int4* row = adj4 + (size_t)m * (N_COLS / 4);
    int4 v[SCAN_IT];
    #pragma unroll
    for (int it = 0; it < SCAN_IT; it++)
        v[it] = row[it * SCAN_TB + tid];

    __syncthreads();

    {
        const int e4 = tid & 31;
        const int dh = tid >> 5;
        float4 acc = make_float4(0.f, 0.f, 0.f, 0.f);
        #pragma unroll
        for (int i = 0; i < 16; i++) {
            const int   d  = dh * 16 + i;
            const float xd = reinterpret_cast<const float*>(s_x)[d];
            const float4 w = W4[(size_t)d * 32 + e4];
            acc.x += xd * w.x; acc.y += xd * w.y;
            acc.z += xd * w.z; acc.w += xd * w.w;
        }
        s_part[dh][e4] = acc;
    }

    int* rowidx = g_idx + (size_t)m * IDXCAP;
    #pragma unroll
    for (int it = 0; it < SCAN_IT; it++) {
        if (v[it].x | v[it].y | v[it].z | v[it].w) {
            int base = (it * SCAN_TB + tid) * 4;
            if (v[it].x) { int p = atomicAdd(&s_cnt, 1); if (p < IDXCAP) rowidx[p] = base;     }
            if (v[it].y) { int p = atomicAdd(&s_cnt, 1); if (p < IDXCAP) rowidx[p] = base + 1; }
            if (v[it].z) { int p = atomicAdd(&s_cnt, 1); if (p < IDXCAP) rowidx[p] = base + 2; }
            if (v[it].w) { int p = atomicAdd(&s_cnt, 1); if (p < IDXCAP) rowidx[p] = base + 3; }
        }
    }
    __syncthreads();

    if (tid == 0) g_cnt[m] = min(s_cnt, IDXCAP);

    if (tid < 32) {
        float4 r = s_part[0][tid];
        #pragma unroll
        for (int dh = 1; dh < 8; dh++) {
            float4 p = s_part[dh][tid];
            r.x += p.x; r.y += p.y; r.z += p.z; r.w += p.w;
        }
        reinterpret_cast<float4*>(g_xa)[(size_t)m * 32 + tid] = r;
    }
}

// ---------------------------------------------------------------------------
// Kernel C v7: transposed scoring, zero shuffles.
//  B: 8 warps stage <=64 neighbor rows into padded smem (coalesced).
//  C: warp 0, lane k = neighbor k (and k+32): full dot from smem
//     (528B pitch -> conflict-free), no SHFL reductions at all.
//  D: warp-0 softmax (proven).
//  E: aggregation from smem, thread = dim (R2-proven, consecutive banks).
// cnt>64 handled by guarded never-taken global paths (data max ~46).
// ---------------------------------------------------------------------------
__global__ void __launch_bounds__(256) attn_compute(const float* __restrict__ xin,
                                                    float*       __restrict__ out) {
    __shared__ float s_rows[RCAP * RPITCH];   // 33.8KB staged rows
    __shared__ float s_xa[D_DIM];
    __shared__ int   s_idx[IDXCAP];
    __shared__ float s_val[IDXCAP];
    __shared__ float s_sum;

    const int m    = blockIdx.x;
    const int tid  = threadIdx.x;
    const int wid  = tid >> 5;
    const int lane = tid & 31;
    const float4* xin4 = reinterpret_cast<const float4*>(xin);

    if (tid < IDXCAP) s_idx[tid] = g_idx[(size_t)m * IDXCAP + tid];
    if (tid < D_DIM)  s_xa[tid]  = g_xa[(size_t)m * D_DIM + tid];
    const int cnt = g_cnt[m];
    __syncthreads();

    if (cnt == 0) {
        if (tid < D_DIM) {
            float acc = 0.f;
            for (int n = 0; n < N_COLS; n++)
                acc += xin[(size_t)n * D_DIM + tid];
            out[(size_t)m * D_DIM + tid] = acc * (1.0f / N_COLS);
        }
        return;
    }

    const int nc = min(cnt, RCAP);

    // ---- B: stage rows into padded smem (warp per row, coalesced) ----
    for (int k = wid; k < nc; k += 8) {
        const float4 a = xin4[(size_t)s_idx[k] * 32 + lane];
        reinterpret_cast<float4*>(&s_rows[k * RPITCH])[lane] = a;  // 528B-aligned
    }
    __syncthreads();

    // ---- C: transposed scores, warp 0, no shuffles ----
    if (wid == 0) {
        const float4* xa4 = reinterpret_cast<const float4*>(s_xa);
        const float4* r0  = reinterpret_cast<const float4*>(&s_rows[lane * RPITCH]);
        float d0 = 0.f;
        #pragma unroll 8
        for (int i = 0; i < 32; i++) {
            const float4 xb = xa4[i];           // broadcast
            const float4 a  = r0[i];            // conflict-free (16k mod 128 distinct)
            d0 = fmaf(a.x, xb.x, fmaf(a.y, xb.y, fmaf(a.z, xb.z, fmaf(a.w, xb.w, d0))));
        }
        if (lane < cnt) s_val[lane] = d0;

        if (cnt > 32) {                         // second neighbor per lane
            const int k2 = lane + 32;
            const float4* r1 = reinterpret_cast<const float4*>(&s_rows[k2 * RPITCH]);
            float d1 = 0.f;
            #pragma unroll 8
            for (int i = 0; i < 32; i++) {
                const float4 xb = xa4[i];
                const float4 a  = r1[i];
                d1 = fmaf(a.x, xb.x, fmaf(a.y, xb.y, fmaf(a.z, xb.z, fmaf(a.w, xb.w, d1))));
            }
            if (k2 < nc) s_val[k2] = d1;
        }
    } else if (cnt > RCAP) {
        // overflow scores (never taken on this data): butterfly from global
        const float4 b = reinterpret_cast<const float4*>(s_xa)[lane];
        for (int k = RCAP + (wid - 1); k < cnt; k += 7) {
            const float4 a = xin4[(size_t)s_idx[k] * 32 + lane];
            float p = fmaf(a.x, b.x, fmaf(a.y, b.y, fmaf(a.z, b.z, a.w * b.w)));
            #pragma unroll
            for (int o = 16; o; o >>= 1) p += __shfl_xor_sync(0xffffffffu, p, o);
            if (lane == 0) s_val[k] = p;
        }
    }
    __syncthreads();

    // ---- D: softmax over cnt entries (warp 0, proven) ----
    if (wid == 0) {
        float mx = -3.0e38f;
        for (int k = lane; k < cnt; k += 32) mx = fmaxf(mx, s_val[k]);
        #pragma unroll
        for (int o = 16; o; o >>= 1) mx = fmaxf(mx, __shfl_xor_sync(0xffffffffu, mx, o));
        float sm = 0.f;
        for (int k = lane; k < cnt; k += 32) {
            float e = __expf((s_val[k] - mx) * INV_T);
            s_val[k] = e;
            sm += e;
        }
        #pragma unroll
        for (int o = 16; o; o >>= 1) sm += __shfl_xor_sync(0xffffffffu, sm, o);
        if (lane == 0) s_sum = sm;
    }
    __syncthreads();

    // ---- E: aggregation from smem, thread = dim (consecutive banks) ----
    if (tid < D_DIM) {
        float acc = 0.f;
        #pragma unroll 4
        for (int k = 0; k < nc; k++)
            acc += s_val[k] * s_rows[k * RPITCH + tid];
        for (int k = nc; k < cnt; k++)                    // never taken
            acc += s_val[k] * xin[(size_t)s_idx[k] * D_DIM + tid];
        out[(size_t)m * D_DIM + tid] = acc / s_sum;
    }
}

// ---------------------------------------------------------------------------
// inputs: 0=xx_anchor [12288,128] f32, 1=input [12288,128] f32,
//         2=adj [12288,12288] i32,    3=weight [128,128] f32
// output: [12288,128] f32
//
// Two serial kernels (streams never co-schedule: R3/R5/R8/R9; full fusion
// starves DRAM: R14). scan+xw fused (R10); attn scoring transposed to kill
// the shuffle-reduction budget that pinned it at ~38.7us.
// ---------------------------------------------------------------------------
extern "C" void kernel_launch(void* const* d_in, const int* in_sizes, int n_in,
                              void* d_out, int out_size) {
    const float* xx_anchor = (const float*)d_in[0];
    const float* input     = (const float*)d_in[1];
    const int*   adj       = (const int*)  d_in[2];
    const float* weight    = (const float*)d_in[3];

    scan_xw_kernel<<<M_ROWS, SCAN_TB>>>((const int4*)adj,
                                        (const float4*)xx_anchor,
                                        (const float4*)weight);
    attn_compute<<<M_ROWS, 256>>>(input, (float*)d_out);
}

// round 17
// speedup vs baseline: 1.0539x; 1.0539x over previous
#include <cuda_runtime.h>

#define M_ROWS 12288
#define N_COLS 12288
#define D_DIM  128
#define INV_T  (1.0f/0.07f)
#define IDXCAP 128
#define NCACHE 32
#define SCAN_TB 256
#define SCAN_IT ((N_COLS/4)/SCAN_TB)   // 12 int4 loads per thread
#define A_ROWS 8                        // was 32: grid 384 -> 1536, occ 16% -> ~64%

// static scratch (allocation-free)
__device__ float g_xa[(size_t)M_ROWS * D_DIM];
__device__ int   g_cnt[M_ROWS];
__device__ int   g_idx[(size_t)M_ROWS * IDXCAP];

// ---------------------------------------------------------------------------
// Kernel S: pure adjacency stream -> compact neighbor lists.
// R2-proven 91.1us @ 84% DRAM. Verbatim.
// ---------------------------------------------------------------------------
__global__ void __launch_bounds__(SCAN_TB) scan_kernel(const int4* __restrict__ adj4) {
    __shared__ int s_cnt;
    const int m   = blockIdx.x;
    const int tid = threadIdx.x;
    const int4* row = adj4 + (size_t)m * (N_COLS / 4);

    if (tid == 0) s_cnt = 0;

    int4 v[SCAN_IT];
    #pragma unroll
    for (int it = 0; it < SCAN_IT; it++)
        v[it] = row[it * SCAN_TB + tid];

    __syncthreads();

    int* rowidx = g_idx + (size_t)m * IDXCAP;
    #pragma unroll
    for (int it = 0; it < SCAN_IT; it++) {
        if (v[it].x | v[it].y | v[it].z | v[it].w) {
            int base = (it * SCAN_TB + tid) * 4;
            if (v[it].x) { int p = atomicAdd(&s_cnt, 1); if (p < IDXCAP) rowidx[p] = base;     }
            if (v[it].y) { int p = atomicAdd(&s_cnt, 1); if (p < IDXCAP) rowidx[p] = base + 1; }
            if (v[it].z) { int p = atomicAdd(&s_cnt, 1); if (p < IDXCAP) rowidx[p] = base + 2; }
            if (v[it].w) { int p = atomicAdd(&s_cnt, 1); if (p < IDXCAP) rowidx[p] = base + 3; }
        }
    }
    __syncthreads();
    if (tid == 0) g_cnt[m] = min(s_cnt, IDXCAP);
}

// ---------------------------------------------------------------------------
// Kernel A: g_xa = X @ W. Proven code; A_ROWS=8 fixes the grid-limited
// occupancy (384 blocks was 2.6/SM = 16%; 1536 -> ~10/SM). W stays in
// registers, re-read per block from L1 (resident after first block).
// Also: a ~20us compute kernel here lets clocks recover from the DRAM
// stream before attn (R4 vs R10: identical attn ran 28.9 vs 38.7us).
// ---------------------------------------------------------------------------
__global__ void __launch_bounds__(128) xw_kernel(const float* __restrict__ X,
                                                 const float* __restrict__ W) {
    __shared__ float Xs[A_ROWS][D_DIM];
    const int e    = threadIdx.x;
    const int row0 = blockIdx.x * A_ROWS;

    for (int r = 0; r < A_ROWS; r++)
        Xs[r][e] = X[(size_t)(row0 + r) * D_DIM + e];

    float wreg[D_DIM];
    #pragma unroll
    for (int d = 0; d < D_DIM; d++)
        wreg[d] = W[d * D_DIM + e];
    __syncthreads();

    for (int r = 0; r < A_ROWS; r++) {
        const float4* x4 = reinterpret_cast<const float4*>(&Xs[r][0]);
        float s0 = 0.f, s1 = 0.f;
        #pragma unroll
        for (int q = 0; q < D_DIM / 4; q++) {
            float4 xv = x4[q];
            s0 += xv.x * wreg[4*q + 0];
            s1 += xv.y * wreg[4*q + 1];
            s0 += xv.z * wreg[4*q + 2];
            s1 += xv.w * wreg[4*q + 3];
        }
        g_xa[(size_t)(row0 + r) * D_DIM + e] = s0 + s1;
    }
}

// ---------------------------------------------------------------------------
// Kernel C (verbatim R8 attn v2 -- measured 28.9us in exactly this
// position): gather-once smem row cache + fused scores, block softmax,
// aggregation.
// ---------------------------------------------------------------------------
__global__ void __launch_bounds__(128) attn_compute(const float* __restrict__ xin,
                                                    float*       __restrict__ out) {
    __shared__ float s_rows[NCACHE][D_DIM];
    __shared__ float s_xa[D_DIM];
    __shared__ int   s_idx[IDXCAP];
    __shared__ float s_val[IDXCAP];
    __shared__ float s_sum;

    const int m    = blockIdx.x;
    const int tid  = threadIdx.x;
    const int wid  = tid >> 5;
    const int lane = tid & 31;

    const int cnt = g_cnt[m];
    s_xa[tid] = g_xa[(size_t)m * D_DIM + tid];
    if (tid < cnt) s_idx[tid] = g_idx[(size_t)m * IDXCAP + tid];
    __syncthreads();

    if (cnt == 0) {
        float acc = 0.f;
        for (int n = 0; n < N_COLS; n++)
            acc += xin[(size_t)n * D_DIM + tid];
        out[(size_t)m * D_DIM + tid] = acc * (1.0f / N_COLS);
        return;
    }

    const int nc = min(cnt, NCACHE);
    const float4 b = reinterpret_cast<const float4*>(s_xa)[lane];

    for (int k = wid; k < nc; k += 4) {
        const float4* r = reinterpret_cast<const float4*>(xin)
                        + (size_t)s_idx[k] * (D_DIM / 4);
        float4 a = r[lane];
        reinterpret_cast<float4*>(&s_rows[k][0])[lane] = a;
        float p = a.x * b.x + a.y * b.y + a.z * b.z + a.w * b.w;
        #pragma unroll
        for (int o = 16; o; o >>= 1) p += __shfl_xor_sync(0xffffffffu, p, o);
        if (lane == 0) s_val[k] = p;
    }
    for (int k = NCACHE + wid; k < cnt; k += 4) {
        const float4* r = reinterpret_cast<const float4*>(xin)
                        + (size_t)s_idx[k] * (D_DIM / 4);
        float4 a = r[lane];
        float p = a.x * b.x + a.y * b.y + a.z * b.z + a.w * b.w;
        #pragma unroll
        for (int o = 16; o; o >>= 1) p += __shfl_xor_sync(0xffffffffu, p, o);
        if (lane == 0) s_val[k] = p;
    }
    __syncthreads();

    if (wid == 0) {
        float mx = -3.0e38f;
        for (int k = lane; k < cnt; k += 32) mx = fmaxf(mx, s_val[k]);
        #pragma unroll
        for (int o = 16; o; o >>= 1) mx = fmaxf(mx, __shfl_xor_sync(0xffffffffu, mx, o));
        float sm = 0.f;
        for (int k = lane; k < cnt; k += 32) {
            float e = __expf((s_val[k] - mx) * INV_T);
            s_val[k] = e;
            sm += e;
        }
        #pragma unroll
        for (int o = 16; o; o >>= 1) sm += __shfl_xor_sync(0xffffffffu, sm, o);
        if (lane == 0) s_sum = sm;
    }
    __syncthreads();

    float acc = 0.f;
    for (int k = 0; k < nc; k++)
        acc += s_val[k] * s_rows[k][tid];
    for (int k = nc; k < cnt; k++)
        acc += s_val[k] * xin[(size_t)s_idx[k] * D_DIM + tid];
    out[(size_t)m * D_DIM + tid] = acc / s_sum;
}

// ---------------------------------------------------------------------------
// inputs: 0=xx_anchor [12288,128] f32, 1=input [12288,128] f32,
//         2=adj [12288,12288] i32,    3=weight [128,128] f32
// output: [12288,128] f32
//
// Three serial kernels in the R4 arrangement (the fastest measured per-part
// decomposition): pure scan stream, occupancy-fixed xw, attn v2.
// Streams never co-schedule (R3/R5/R8/R9); full fusion starves DRAM (R14);
// scan+xw fusion costs attn +10us downstream (R10 vs R4, DVFS-consistent).
// ---------------------------------------------------------------------------
extern "C" void kernel_launch(void* const* d_in, const int* in_sizes, int n_in,
                              void* d_out, int out_size) {
    const float* xx_anchor = (const float*)d_in[0];
    const float* input     = (const float*)d_in[1];
    const int*   adj       = (const int*)  d_in[2];
    const float* weight    = (const float*)d_in[3];
    float*       out       = (float*)d_out;

    scan_kernel<<<M_ROWS, SCAN_TB>>>((const int4*)adj);
    xw_kernel<<<M_ROWS / A_ROWS, 128>>>(xx_anchor, weight);
    attn_compute<<<M_ROWS, 128>>>(input, out);
}